// round 1
// baseline (speedup 1.0000x reference)
#include <cuda_runtime.h>
#include <math.h>

#define BDIM 4096
#define RDIM 64
#define DDIM 512
#define BB 32          // batch rows per block
#define DC 64          // d-chunk staged in shared
#define NCHUNK (DDIM / DC)
#define NBLOCK (BDIM / BB)   // 128

__device__ float g_partial[NBLOCK];

__global__ __launch_bounds__(256, 1)
void dist_kernel(const float* __restrict__ w,
                 const float* __restrict__ e,
                 const float* __restrict__ label,
                 float* __restrict__ out)
{
    // w tile transposed: [d][b], stride 33 -> conflict-free lane reads
    __shared__ float w_sT[DC][33];
    // e tile: row stride 68 floats (17 float4) -> aligned float4 broadcasts
    __shared__ __align__(16) float e_s[RDIM * 68];
    // full dist^2 tile for later gather of dist2[y]
    __shared__ float dist_s[RDIM][33];
    // per-warp partial reductions
    __shared__ float red_m1[8][32], red_m2[8][32], red_lm[8][32];
    __shared__ int   red_i1[8][32], red_i2[8][32], red_li[8][32];
    __shared__ int   idx1_s[32];

    const int tid  = threadIdx.x;
    const int lane = tid & 31;
    const int wid  = tid >> 5;
    const int b0   = blockIdx.x * BB;
    const int r0   = wid * 8;              // this warp's relation group
    const int sub  = lane >> 3;            // ne slice (0..3)
    const int rj   = lane & 7;             // ne relation within group

    float acc[8];
#pragma unroll
    for (int j = 0; j < 8; j++) acc[j] = 0.f;
    float acc_nw  = 0.f;   // ||w_b||^2 (b = b0+lane), replicated per warp
    float ne_part = 0.f;   // partial ||e_{r0+rj}||^2 over d-slice `sub`

    const float4* e_s4 = reinterpret_cast<const float4*>(e_s);

    for (int c = 0; c < NCHUNK; c++) {
        const int d0 = c * DC;

        // ---- stage w transposed (coalesced LDG, conflict-free STS) ----
        for (int i = tid; i < BB * DC; i += 256) {
            int bl = i >> 6;            // DC == 64
            int dc = i & (DC - 1);
            w_sT[dc][bl] = w[(size_t)(b0 + bl) * DDIM + d0 + dc];
        }
        // ---- stage e (float4, coalesced) ----
        {
            const float4* eg = reinterpret_cast<const float4*>(e);
            float4* es4w = reinterpret_cast<float4*>(e_s);
            for (int i = tid; i < RDIM * (DC / 4); i += 256) {
                int r  = i >> 4;        // DC/4 == 16
                int d4 = i & 15;
                es4w[r * 17 + d4] = eg[(size_t)r * (DDIM / 4) + (d0 >> 2) + d4];
            }
        }
        __syncthreads();

        // ---- ||e||^2 partial: lane-sliced, 4 float4 per chunk ----
#pragma unroll
        for (int k = 0; k < 4; k++) {
            float4 e4 = e_s4[(r0 + rj) * 17 + sub * 4 + k];
            ne_part = fmaf(e4.x, e4.x, ne_part);
            ne_part = fmaf(e4.y, e4.y, ne_part);
            ne_part = fmaf(e4.z, e4.z, ne_part);
            ne_part = fmaf(e4.w, e4.w, ne_part);
        }

        // ---- main dot loop: 4 d's per group ----
#pragma unroll
        for (int d = 0; d < DC; d += 4) {
            float w0 = w_sT[d + 0][lane];
            float w1 = w_sT[d + 1][lane];
            float w2 = w_sT[d + 2][lane];
            float w3 = w_sT[d + 3][lane];
            acc_nw = fmaf(w0, w0, acc_nw);
            acc_nw = fmaf(w1, w1, acc_nw);
            acc_nw = fmaf(w2, w2, acc_nw);
            acc_nw = fmaf(w3, w3, acc_nw);
            const int d4 = d >> 2;
#pragma unroll
            for (int j = 0; j < 8; j++) {
                float4 e4 = e_s4[(r0 + j) * 17 + d4];   // warp-uniform broadcast
                acc[j] = fmaf(w0, e4.x, acc[j]);
                acc[j] = fmaf(w1, e4.y, acc[j]);
                acc[j] = fmaf(w2, e4.z, acc[j]);
                acc[j] = fmaf(w3, e4.w, acc[j]);
            }
        }
        __syncthreads();
    }

    // nw is replicated per warp: acc_nw already holds ||w_{b0+lane}||^2.
    // Reduce ne slices: lanes {l, l^8, l^16, l^24} share a relation.
    ne_part += __shfl_xor_sync(0xFFFFFFFFu, ne_part, 16);
    ne_part += __shfl_xor_sync(0xFFFFFFFFu, ne_part, 8);
    float ne_j[8];
#pragma unroll
    for (int j = 0; j < 8; j++)
        ne_j[j] = __shfl_sync(0xFFFFFFFFu, ne_part, j);  // lane j holds rel r0+j

    // ---- dist^2, local top-2 (first-index tie-break) ----
    float m1 = -1e30f, m2 = -1e30f;
    int   i1 = r0, i2 = r0;
#pragma unroll
    for (int j = 0; j < 8; j++) {
        float d2 = fmaxf(fmaf(-2.f, acc[j], acc_nw + ne_j[j]), 0.f);
        dist_s[r0 + j][lane] = d2;
        if (d2 > m1)      { m2 = m1; i2 = i1; m1 = d2; i1 = r0 + j; }
        else if (d2 > m2) { m2 = d2; i2 = r0 + j; }
    }

    // ---- label local argmax over this warp's 8 relations ----
    {
        const float* lp = label + (size_t)(b0 + lane) * RDIM + r0;
        float4 la = reinterpret_cast<const float4*>(lp)[0];
        float4 lb = reinterpret_cast<const float4*>(lp)[1];
        float lv[8] = {la.x, la.y, la.z, la.w, lb.x, lb.y, lb.z, lb.w};
        float lm = lv[0]; int li = r0;
#pragma unroll
        for (int j = 1; j < 8; j++)
            if (lv[j] > lm) { lm = lv[j]; li = r0 + j; }
        red_lm[wid][lane] = lm;
        red_li[wid][lane] = li;
    }
    red_m1[wid][lane] = m1;  red_i1[wid][lane] = i1;
    red_m2[wid][lane] = m2;  red_i2[wid][lane] = i2;
    __syncthreads();

    // ---- per-row merge across the 8 warps (warp 0, lane = row) ----
    if (wid == 0) {
        float v1 = red_m1[0][lane]; int ix1 = red_i1[0][lane];
        float v2 = red_m2[0][lane]; int ix2 = red_i2[0][lane];
        float LV = red_lm[0][lane]; int LI  = red_li[0][lane];
#pragma unroll
        for (int g = 1; g < 8; g++) {
            float a1 = red_m1[g][lane]; int aj1 = red_i1[g][lane];
            float a2 = red_m2[g][lane]; int aj2 = red_i2[g][lane];
            if (a1 > v1) {
                // merged second = max(v1, a2); tie prefers v1 (lower index)
                if (a2 > v1) { v2 = a2; ix2 = aj2; }
                else         { v2 = v1; ix2 = ix1; }
                v1 = a1; ix1 = aj1;
            } else if (a1 > v2) {
                v2 = a1; ix2 = aj1;
            }
            float al = red_lm[g][lane];
            if (al > LV) { LV = al; LI = red_li[g][lane]; }
        }
        const int y = LI;
        float plus2  = dist_s[y][lane];
        float minus2 = (ix1 == y) ? v2 : v1;
        float loss_b = 1.f + sqrtf(plus2) - sqrtf(minus2);
        idx1_s[lane] = ix1;
        (void)ix2;
#pragma unroll
        for (int off = 16; off; off >>= 1)
            loss_b += __shfl_xor_sync(0xFFFFFFFFu, loss_b, off);
        if (lane == 0) g_partial[blockIdx.x] = loss_b;
    }
    __syncthreads();

    // ---- coalesced one-hot pred write (float4) ----
    {
        float4* op = reinterpret_cast<float4*>(out + (size_t)b0 * RDIM);
#pragma unroll
        for (int k = 0; k < 2; k++) {
            int i  = tid * 8 + k * 4;        // element offset in block region
            int bl = i >> 6;
            int r  = i & 63;
            int p  = idx1_s[bl];
            float4 v;
            v.x = (r + 0 == p) ? 1.f : 0.f;
            v.y = (r + 1 == p) ? 1.f : 0.f;
            v.z = (r + 2 == p) ? 1.f : 0.f;
            v.w = (r + 3 == p) ? 1.f : 0.f;
            op[tid * 2 + k] = v;
        }
    }
}

__global__ void finalize_kernel(float* __restrict__ out, int out_size)
{
    __shared__ float s[NBLOCK];
    int t = threadIdx.x;
    s[t] = g_partial[t];
    __syncthreads();
#pragma unroll
    for (int off = NBLOCK / 2; off > 0; off >>= 1) {
        if (t < off) s[t] += s[t + off];
        __syncthreads();
    }
    if (t == 0) out[out_size - 1] = s[0] * (1.0f / (float)BDIM);
}

extern "C" void kernel_launch(void* const* d_in, const int* in_sizes, int n_in,
                              void* d_out, int out_size)
{
    const float* w     = (const float*)d_in[0];   // [4096, 512]
    const float* e     = (const float*)d_in[1];   // [64, 512]
    const float* label = (const float*)d_in[2];   // [4096, 64]
    float* out = (float*)d_out;                   // pred [4096*64] ++ loss [1]

    dist_kernel<<<NBLOCK, 256>>>(w, e, label, out);
    finalize_kernel<<<1, NBLOCK>>>(out, out_size);
}